// round 2
// baseline (speedup 1.0000x reference)
#include <cuda_runtime.h>
#include <cstdint>

#define S_LEN   2048
#define IN_DIM  512
#define OUT_DIM 512
#define NH      16
#define NKV     4
#define HD      64
#define BM      64
#define BN      64
#define KP      68   // padded pitch for transposed K tile (4-way instead of 32-way store conflicts)

// Scratch (no cudaMalloc allowed anywhere)
__device__ float g_q[S_LEN * NH * HD];     // [S, H*64]
__device__ float g_k[S_LEN * NKV * HD];    // [S, KV*64]
__device__ float g_v[S_LEN * NKV * HD];    // [S, KV*64]
__device__ float g_o[S_LEN * NH * HD];     // [S, H*64]

// ---------------------------------------------------------------------------
// Generic 64x64 GEMM tile body: C[m0+i][c0+j] = sum_k A[m0+i][k] * Bn[j][k]
// A row-major [M,K], Bn row-major [64,K] (pre-offset), C row-major pitch ldc.
// 256 threads, 4x4 micro-tile per thread, k-chunks of 16.
// ---------------------------------------------------------------------------
__device__ __forceinline__ void gemm_body(
    const float* __restrict__ A, const float* __restrict__ Bn,
    float* __restrict__ C, int K, int ldc, int m0)
{
    __shared__ float As[16][68];   // As[kk][i]
    __shared__ float Bs[16][68];   // Bs[kk][j]
    const int tid = threadIdx.x;
    const int tx = tid & 15, ty = tid >> 4;
    const int r0 = ty * 4, c0 = tx * 4;
    const int kk = tid & 15, rb = tid >> 4;

    float acc[4][4] = {};

    for (int k0 = 0; k0 < K; k0 += 16) {
        #pragma unroll
        for (int rep = 0; rep < 4; rep++) {
            int i = rb + rep * 16;
            As[kk][i] = A[(size_t)(m0 + i) * K + k0 + kk];
            Bs[kk][i] = Bn[(size_t)i * K + k0 + kk];
        }
        __syncthreads();
        #pragma unroll
        for (int ks = 0; ks < 16; ks++) {
            float4 a4 = *(const float4*)&As[ks][r0];
            float4 b4 = *(const float4*)&Bs[ks][c0];
            float av[4] = {a4.x, a4.y, a4.z, a4.w};
            float bv[4] = {b4.x, b4.y, b4.z, b4.w};
            #pragma unroll
            for (int i = 0; i < 4; i++)
                #pragma unroll
                for (int j = 0; j < 4; j++)
                    acc[i][j] += av[i] * bv[j];
        }
        __syncthreads();
    }
    #pragma unroll
    for (int i = 0; i < 4; i++) {
        float4 o4 = {acc[i][0], acc[i][1], acc[i][2], acc[i][3]};
        *(float4*)&C[(size_t)(m0 + r0 + i) * ldc + c0] = o4;
    }
}

// Fused QKV projection: grid (32, 24). by 0..15 -> Q, 16..19 -> K, 20..23 -> V.
__global__ __launch_bounds__(256)
void qkv_kernel(const float* __restrict__ x,
                const float* __restrict__ wq,
                const float* __restrict__ wk,
                const float* __restrict__ wv)
{
    const int by = blockIdx.y;
    const float* B; float* C; int ldc, coff;
    if (by < 16)      { B = wq; C = g_q; ldc = NH * HD;  coff = by * 64; }
    else if (by < 20) { B = wk; C = g_k; ldc = NKV * HD; coff = (by - 16) * 64; }
    else              { B = wv; C = g_v; ldc = NKV * HD; coff = (by - 20) * 64; }
    gemm_body(x, B + (size_t)coff * IN_DIM, C + coff, IN_DIM, ldc, blockIdx.x * 64);
}

// Output projection: out = g_o[2048,1024] @ Wo^T[512,1024]. grid (32, 8).
__global__ __launch_bounds__(256)
void out_gemm_kernel(const float* __restrict__ wo, float* __restrict__ out)
{
    const int n0 = blockIdx.y * 64;
    gemm_body(g_o, wo + (size_t)n0 * (NH * HD), out + n0, NH * HD, OUT_DIM, blockIdx.x * 64);
}

// ---------------------------------------------------------------------------
// Flash attention (fp32). grid (32, 16): (s-block reversed, head).
// Each block: Q tile [64,64] for head h, loops kv heads 0..3, t-tiles 0..bs
// (causal skip), online softmax, accumulates averaged output into g_o.
// Dynamic smem: Qt[64][64] + Kt/Pt[64][68] + Vs[64][64] = 50176 bytes.
// ---------------------------------------------------------------------------
__global__ __launch_bounds__(256)
void attn_kernel()
{
    extern __shared__ float sm[];
    float* Qt = sm;                 // Qt[d][i]   (transposed Q, pre-scaled)
    float* Kt = Qt + 64 * 64;       // Kt[d][j]   (transposed K), reused as Pt[j][i]
    float* Vs = Kt + 64 * KP;       // Vs[j][d]

    const int bs = (int)gridDim.x - 1 - (int)blockIdx.x;   // heavy blocks first
    const int h  = blockIdx.y;
    const int s0 = bs * BM;
    const int tid = threadIdx.x;
    const int tx = tid & 15, ty = tid >> 4;
    const int r0 = ty * 4, c0 = tx * 4;

    // Load Q tile transposed, scaled by 1/sqrt(64)
    {
        const int d = tid & 63, ib = tid >> 6;
        const float* qp = g_q + (size_t)s0 * (NH * HD) + h * HD + d;
        #pragma unroll
        for (int rep = 0; rep < 16; rep++) {
            int i = ib * 16 + rep;
            Qt[d * 64 + i] = qp[(size_t)i * (NH * HD)] * 0.125f;
        }
    }
    __syncthreads();

    float accT[4][4] = {};   // final (sum over kv of normalized attn) per thread

    for (int kv = 0; kv < NKV; kv++) {
        float acc[4][4] = {};
        float mrow[4] = {-1e30f, -1e30f, -1e30f, -1e30f};
        float lrow[4] = {};

        for (int t = 0; t <= bs; t++) {
            // Load K (transposed) and V tiles for this kv head
            {
                const int d = tid & 63, jb = tid >> 6;
                const float* kp = g_k + (size_t)(t * BN) * (NKV * HD) + kv * HD + d;
                const float* vp = g_v + (size_t)(t * BN) * (NKV * HD) + kv * HD + d;
                #pragma unroll
                for (int rep = 0; rep < 16; rep++) {
                    int j = jb * 16 + rep;
                    Kt[d * KP + j] = kp[(size_t)j * (NKV * HD)];
                    Vs[j * 64 + d] = vp[(size_t)j * (NKV * HD)];
                }
            }
            __syncthreads();

            // Scores S = Q K^T (4x4 per thread)
            float sc[4][4] = {};
            #pragma unroll 8
            for (int d = 0; d < 64; d++) {
                float4 q4 = *(const float4*)&Qt[d * 64 + r0];
                float4 k4 = *(const float4*)&Kt[d * KP + c0];
                float qv[4] = {q4.x, q4.y, q4.z, q4.w};
                float kw[4] = {k4.x, k4.y, k4.z, k4.w};
                #pragma unroll
                for (int i = 0; i < 4; i++)
                    #pragma unroll
                    for (int j = 0; j < 4; j++)
                        sc[i][j] += qv[i] * kw[j];
            }
            // Causal mask on diagonal tile
            if (t == bs) {
                #pragma unroll
                for (int i = 0; i < 4; i++)
                    #pragma unroll
                    for (int j = 0; j < 4; j++)
                        if (c0 + j > r0 + i) sc[i][j] = -1e30f;
            }

            // Online softmax: row reductions across the 16 tx-lanes (same ty)
            float p[4][4];
            #pragma unroll
            for (int i = 0; i < 4; i++) {
                float mnew = fmaxf(fmaxf(sc[i][0], sc[i][1]), fmaxf(sc[i][2], sc[i][3]));
                #pragma unroll
                for (int msk = 8; msk; msk >>= 1)
                    mnew = fmaxf(mnew, __shfl_xor_sync(0xffffffffu, mnew, msk));
                mnew = fmaxf(mnew, mrow[i]);
                float scale = __expf(mrow[i] - mnew);
                mrow[i] = mnew;
                float rsum = 0.f;
                #pragma unroll
                for (int j = 0; j < 4; j++) { p[i][j] = __expf(sc[i][j] - mnew); rsum += p[i][j]; }
                #pragma unroll
                for (int msk = 8; msk; msk >>= 1)
                    rsum += __shfl_xor_sync(0xffffffffu, rsum, msk);
                lrow[i] = lrow[i] * scale + rsum;
                #pragma unroll
                for (int j = 0; j < 4; j++) acc[i][j] *= scale;
            }
            __syncthreads();   // all reads of Kt done before overwriting with Pt

            // Write P^T into Kt buffer: Pt[j][i]
            #pragma unroll
            for (int j = 0; j < 4; j++) {
                float4 p4 = {p[0][j], p[1][j], p[2][j], p[3][j]};
                *(float4*)&Kt[(c0 + j) * KP + r0] = p4;
            }
            __syncthreads();

            // O += P V : acc[i][dd] += Pt[j][r0+i] * Vs[j][c0+dd]
            #pragma unroll 8
            for (int j = 0; j < BN; j++) {
                float4 p4 = *(const float4*)&Kt[j * KP + r0];
                float4 v4 = *(const float4*)&Vs[j * 64 + c0];
                float pv[4] = {p4.x, p4.y, p4.z, p4.w};
                float vv[4] = {v4.x, v4.y, v4.z, v4.w};
                #pragma unroll
                for (int i = 0; i < 4; i++)
                    #pragma unroll
                    for (int dd = 0; dd < 4; dd++)
                        acc[i][dd] += pv[i] * vv[dd];
            }
            __syncthreads();   // before next tile load overwrites Kt/Vs
        }

        // Fold this kv head's normalized output
        #pragma unroll
        for (int i = 0; i < 4; i++) {
            float inv = 1.0f / lrow[i];
            #pragma unroll
            for (int dd = 0; dd < 4; dd++)
                accT[i][dd] += acc[i][dd] * inv;
        }
    }

    // Average over KV heads and store
    #pragma unroll
    for (int i = 0; i < 4; i++) {
        float4 o4 = {accT[i][0] * 0.25f, accT[i][1] * 0.25f,
                     accT[i][2] * 0.25f, accT[i][3] * 0.25f};
        *(float4*)&g_o[(size_t)(s0 + r0 + i) * (NH * HD) + h * HD + c0] = o4;
    }
}

// ---------------------------------------------------------------------------
extern "C" void kernel_launch(void* const* d_in, const int* in_sizes, int n_in,
                              void* d_out, int out_size)
{
    const float* x  = (const float*)d_in[0];
    const float* Wq = (const float*)d_in[1];
    const float* Wk = (const float*)d_in[2];
    const float* Wv = (const float*)d_in[3];
    const float* Wo = (const float*)d_in[4];
    float* out = (float*)d_out;

    static_assert(sizeof(float) == 4, "");
    const int ATTN_SMEM = (64 * 64 + 64 * KP + 64 * 64) * 4;   // 50176 B

    cudaFuncSetAttribute(attn_kernel,
                         cudaFuncAttributeMaxDynamicSharedMemorySize, ATTN_SMEM);

    qkv_kernel<<<dim3(32, 24), 256>>>(x, Wq, Wk, Wv);
    attn_kernel<<<dim3(32, 16), 256, ATTN_SMEM>>>();
    out_gemm_kernel<<<dim3(32, 8), 256>>>(Wo, out);
}

// round 6
// speedup vs baseline: 3.6442x; 3.6442x over previous
#include <cuda_runtime.h>
#include <cuda_fp16.h>
#include <cstdint>

#define S_LEN   2048
#define IN_DIM  512
#define OUT_DIM 512
#define NH      16
#define NKV     4
#define HD      64

// Q pre-scale: 1/sqrt(64) * log2(e)  (softmax done with ex2)
#define SCALE_Q 0.18033688011112042f

// ---------------- scratch (__device__ globals; no cudaMalloc allowed) -------
__device__ __half g_qh[S_LEN * NH * HD];     // [2048][1024] fp16 (pre-scaled by SCALE_Q)
__device__ __half g_kh[S_LEN * NKV * HD];    // [2048][256]  fp16
__device__ __half g_vh[S_LEN * NKV * HD];    // [2048][256]  fp16
__device__ float g_opart[NKV][S_LEN * NH * HD];   // per-kv attention partials
__device__ float g_o[S_LEN * NH * HD];            // reduced attention output

__device__ __forceinline__ float ex2f(float x) {
    float y; asm("ex2.approx.ftz.f32 %0, %1;" : "=f"(y) : "f"(x)); return y;
}

// m16n8k16 fp16 MMA, fp32 accumulate: C += A x B
__device__ __forceinline__ void mma16816(float* c, const uint32_t* a,
                                         uint32_t b0, uint32_t b1) {
    asm volatile(
        "mma.sync.aligned.m16n8k16.row.col.f32.f16.f16.f32 "
        "{%0,%1,%2,%3}, {%4,%5,%6,%7}, {%8,%9}, {%0,%1,%2,%3};"
        : "+f"(c[0]), "+f"(c[1]), "+f"(c[2]), "+f"(c[3])
        : "r"(a[0]), "r"(a[1]), "r"(a[2]), "r"(a[3]), "r"(b0), "r"(b1));
}

__device__ __forceinline__ uint32_t packh2(float a, float b) {
    __half2 h = __floats2half2_rn(a, b);
    return *(uint32_t*)&h;
}

// ---------------------------------------------------------------------------
// fp32 GEMM tile body (64x64, 256 threads) for QKV + output projection.
// ---------------------------------------------------------------------------
struct QkvEpi {
    __half* Cb; int ldc; float scale;
    __device__ __forceinline__ void operator()(float (&acc)[4][4], int row, int col) const {
        #pragma unroll
        for (int i = 0; i < 4; i++) {
            uint2 u = { packh2(acc[i][0] * scale, acc[i][1] * scale),
                        packh2(acc[i][2] * scale, acc[i][3] * scale) };
            *(uint2*)&Cb[(size_t)(row + i) * ldc + col] = u;
        }
    }
};

struct OutEpi {
    float* outb;
    __device__ __forceinline__ void operator()(float (&acc)[4][4], int row, int col) const {
        #pragma unroll
        for (int i = 0; i < 4; i++) {
            float4 o4 = {acc[i][0], acc[i][1], acc[i][2], acc[i][3]};
            *(float4*)&outb[(size_t)(row + i) * OUT_DIM + col] = o4;
        }
    }
};

template <typename EPI>
__device__ __forceinline__ void gemm_body(
    const float* __restrict__ A, const float* __restrict__ Bn,
    int K, int m0, EPI epi)
{
    __shared__ float As[16][68];
    __shared__ float Bs[16][68];
    const int tid = threadIdx.x;
    const int tx = tid & 15, ty = tid >> 4;
    const int r0 = ty * 4, c0 = tx * 4;
    const int kk = tid & 15, rb = tid >> 4;

    float acc[4][4] = {};
    for (int k0 = 0; k0 < K; k0 += 16) {
        #pragma unroll
        for (int rep = 0; rep < 4; rep++) {
            int i = rb + rep * 16;
            As[kk][i] = A[(size_t)(m0 + i) * K + k0 + kk];
            Bs[kk][i] = Bn[(size_t)i * K + k0 + kk];
        }
        __syncthreads();
        #pragma unroll
        for (int ks = 0; ks < 16; ks++) {
            float4 a4 = *(const float4*)&As[ks][r0];
            float4 b4 = *(const float4*)&Bs[ks][c0];
            float av[4] = {a4.x, a4.y, a4.z, a4.w};
            float bv[4] = {b4.x, b4.y, b4.z, b4.w};
            #pragma unroll
            for (int i = 0; i < 4; i++)
                #pragma unroll
                for (int j = 0; j < 4; j++)
                    acc[i][j] += av[i] * bv[j];
        }
        __syncthreads();
    }
    epi(acc, m0 + r0, c0);
}

// QKV projection -> fp16 outputs. grid (32, 24).
__global__ __launch_bounds__(256)
void qkv_kernel(const float* __restrict__ x,
                const float* __restrict__ wq,
                const float* __restrict__ wk,
                const float* __restrict__ wv)
{
    const int by = blockIdx.y;
    const float* B; __half* C; int ldc, coff; float scale;
    if (by < 16)      { B = wq; C = g_qh; ldc = NH * HD;  coff = by * 64;        scale = SCALE_Q; }
    else if (by < 20) { B = wk; C = g_kh; ldc = NKV * HD; coff = (by - 16) * 64; scale = 1.0f; }
    else              { B = wv; C = g_vh; ldc = NKV * HD; coff = (by - 20) * 64; scale = 1.0f; }
    QkvEpi epi = { C + coff, ldc, scale };
    gemm_body(x, B + (size_t)coff * IN_DIM, IN_DIM, blockIdx.x * 64, epi);
}

// Output projection: out = g_o[2048,1024] @ Wo^T. grid (32, 8).
__global__ __launch_bounds__(256)
void out_gemm_kernel(const float* __restrict__ wo, float* __restrict__ out)
{
    const int n0 = blockIdx.y * 64;
    OutEpi epi = { out + n0 };
    gemm_body(g_o, wo + (size_t)n0 * (NH * HD), NH * HD, blockIdx.x * 64, epi);
}

// Sum kv partials. grid 2048 x 256 (float4 per thread).
__global__ __launch_bounds__(256)
void reduce_o_kernel()
{
    int i = blockIdx.x * 256 + threadIdx.x;
    const float4* p0 = (const float4*)g_opart[0];
    const float4* p1 = (const float4*)g_opart[1];
    const float4* p2 = (const float4*)g_opart[2];
    const float4* p3 = (const float4*)g_opart[3];
    float4 a = p0[i], b = p1[i], c = p2[i], d = p3[i];
    float4 r = { a.x + b.x + c.x + d.x, a.y + b.y + c.y + d.y,
                 a.z + b.z + c.z + d.z, a.w + b.w + c.w + d.w };
    ((float4*)g_o)[i] = r;
}

// ---------------------------------------------------------------------------
// mma.sync flash attention. grid (32 s-blocks heavy-first, 16 h, 4 kv),
// 128 threads (4 warps x 16 q-rows = 64 q-rows per CTA).
// sK[key][d] and sV[d][j] in smem, pitch 72 halves (conflict-free B-frag LDS).
// ---------------------------------------------------------------------------
#define KPITCH 72

__global__ __launch_bounds__(128)
void attn_kernel()
{
    __shared__ __align__(16) __half sK[64 * KPITCH];   // [key][d]
    __shared__ __align__(16) __half sV[64 * KPITCH];   // [d][j]

    const int tid = threadIdx.x;
    const int w   = tid >> 5;
    const int l   = tid & 31;
    const int lr  = l >> 2;          // fragment row id (0..7)
    const int lc  = l & 3;           // fragment col id (0..3)
    const int bs  = 31 - (int)blockIdx.x;   // heavy blocks first
    const int h   = blockIdx.y;
    const int kv  = blockIdx.z;
    const int s0  = bs * 64;
    const int T   = bs + 1;

    // ---- Q A-fragments, loaded once (row-major m16k16 layout) -------------
    uint32_t qf[4][4];
    {
        const __half* qb = g_qh + (size_t)(s0 + w * 16) * (NH * HD) + h * HD;
        #pragma unroll
        for (int ks = 0; ks < 4; ks++) {
            int k0 = ks * 16 + lc * 2;
            qf[ks][0] = *(const uint32_t*)(qb + (size_t)lr * (NH * HD) + k0);
            qf[ks][1] = *(const uint32_t*)(qb + (size_t)(lr + 8) * (NH * HD) + k0);
            qf[ks][2] = *(const uint32_t*)(qb + (size_t)lr * (NH * HD) + k0 + 8);
            qf[ks][3] = *(const uint32_t*)(qb + (size_t)(lr + 8) * (NH * HD) + k0 + 8);
        }
    }

    float oacc[8][4] = {};
    float lsum0 = 0.f, lsum1 = 0.f;
    const int row0 = s0 + w * 16 + lr;
    const int row1 = row0 + 8;

    for (int t = 0; t < T; t++) {
        __syncthreads();   // prior tile's smem reads complete

        // ---- load K tile [64 keys][64 d] into sK (pitch 72) ---------------
        {
            int key = tid >> 1, hf = tid & 1;
            const __half* src = g_kh + (size_t)(t * 64 + key) * (NKV * HD) + kv * HD + hf * 32;
            uint4* dst = (uint4*)(sK + key * KPITCH + hf * 32);
            const uint4* s4 = (const uint4*)src;
            dst[0] = s4[0]; dst[1] = s4[1]; dst[2] = s4[2]; dst[3] = s4[3];
        }
        // ---- load V tile transposed: sV[d][j], pitch 72 -------------------
        {
            int j2 = (tid & 31) * 2;      // j, j+1
            int dg = tid >> 5;            // d range dg*16 .. +15
            const __half* v0 = g_vh + (size_t)(t * 64 + j2) * (NKV * HD) + kv * HD + dg * 16;
            uint4 a0 = *(const uint4*)(v0);
            uint4 a1 = *(const uint4*)(v0 + 8);
            uint4 b0 = *(const uint4*)(v0 + NKV * HD);
            uint4 b1 = *(const uint4*)(v0 + NKV * HD + 8);
            const __half* ea0 = (const __half*)&a0;
            const __half* ea1 = (const __half*)&a1;
            const __half* eb0 = (const __half*)&b0;
            const __half* eb1 = (const __half*)&b1;
            uint32_t* sVw = (uint32_t*)sV;
            #pragma unroll
            for (int dd = 0; dd < 8; dd++) {
                __half2 p0; p0.x = ea0[dd]; p0.y = eb0[dd];
                __half2 p1; p1.x = ea1[dd]; p1.y = eb1[dd];
                sVw[(dg * 16 + dd) * (KPITCH / 2) + (tid & 31)] = *(uint32_t*)&p0;
                sVw[(dg * 16 + 8 + dd) * (KPITCH / 2) + (tid & 31)] = *(uint32_t*)&p1;
            }
        }
        __syncthreads();

        // ---- S = Q K^T : 8 n-frags x 4 k-steps ----------------------------
        float sc[8][4] = {};
        #pragma unroll
        for (int ks = 0; ks < 4; ks++) {
            #pragma unroll
            for (int nf = 0; nf < 8; nf++) {
                const __half* kb = sK + (nf * 8 + lr) * KPITCH + ks * 16 + lc * 2;
                uint32_t b0 = *(const uint32_t*)kb;
                uint32_t b1 = *(const uint32_t*)(kb + 8);
                mma16816(sc[nf], qf[ks], b0, b1);
            }
        }

        // ---- mask + exp (un-normalized) + repack as PV A-frags ------------
        uint32_t pf[4][4];
        const int jb = t * 64;
        #pragma unroll
        for (int nf = 0; nf < 8; nf++) {
            int j0 = jb + nf * 8 + lc * 2;
            float p00 = (j0     <= row0) ? ex2f(sc[nf][0]) : 0.f;
            float p01 = (j0 + 1 <= row0) ? ex2f(sc[nf][1]) : 0.f;
            float p10 = (j0     <= row1) ? ex2f(sc[nf][2]) : 0.f;
            float p11 = (j0 + 1 <= row1) ? ex2f(sc[nf][3]) : 0.f;
            lsum0 += p00 + p01;
            lsum1 += p10 + p11;
            pf[nf >> 1][(nf & 1) * 2 + 0] = packh2(p00, p01);
            pf[nf >> 1][(nf & 1) * 2 + 1] = packh2(p10, p11);
        }

        // ---- O += P V : 8 d-frags x 4 k-steps (j) -------------------------
        #pragma unroll
        for (int ks = 0; ks < 4; ks++) {
            #pragma unroll
            for (int df = 0; df < 8; df++) {
                const __half* vb = sV + (df * 8 + lr) * KPITCH + ks * 16 + lc * 2;
                uint32_t b0 = *(const uint32_t*)vb;
                uint32_t b1 = *(const uint32_t*)(vb + 8);
                mma16816(oacc[df], pf[ks], b0, b1);
            }
        }
    }

    // ---- row-sum reduction across the 4 lanes sharing each row ------------
    lsum0 += __shfl_xor_sync(0xffffffffu, lsum0, 1);
    lsum0 += __shfl_xor_sync(0xffffffffu, lsum0, 2);
    lsum1 += __shfl_xor_sync(0xffffffffu, lsum1, 1);
    lsum1 += __shfl_xor_sync(0xffffffffu, lsum1, 2);
    const float inv0 = 0.25f / lsum0;
    const float inv1 = 0.25f / lsum1;

    // ---- store per-kv partial O -------------------------------------------
    float* d0 = g_opart[kv] + (size_t)row0 * (NH * HD) + h * HD + lc * 2;
    float* d1 = g_opart[kv] + (size_t)row1 * (NH * HD) + h * HD + lc * 2;
    #pragma unroll
    for (int df = 0; df < 8; df++) {
        float2 u0 = { oacc[df][0] * inv0, oacc[df][1] * inv0 };
        float2 u1 = { oacc[df][2] * inv1, oacc[df][3] * inv1 };
        *(float2*)(d0 + df * 8) = u0;
        *(float2*)(d1 + df * 8) = u1;
    }
}

// ---------------------------------------------------------------------------
extern "C" void kernel_launch(void* const* d_in, const int* in_sizes, int n_in,
                              void* d_out, int out_size)
{
    const float* x  = (const float*)d_in[0];
    const float* Wq = (const float*)d_in[1];
    const float* Wk = (const float*)d_in[2];
    const float* Wv = (const float*)d_in[3];
    const float* Wo = (const float*)d_in[4];
    float* out = (float*)d_out;

    qkv_kernel<<<dim3(32, 24), 256>>>(x, Wq, Wk, Wv);
    attn_kernel<<<dim3(32, 16, 4), 128>>>();
    reduce_o_kernel<<<2048, 256>>>();
    out_gemm_kernel<<<dim3(32, 8), 256>>>(Wo, out);
}

// round 7
// speedup vs baseline: 4.0750x; 1.1182x over previous
#include <cuda_runtime.h>
#include <cuda_fp16.h>
#include <cstdint>

#define S_LEN   2048
#define IN_DIM  512
#define OUT_DIM 512
#define NH      16
#define NKV     4
#define HD      64

// Q pre-scale: 1/sqrt(64) * log2(e)  (softmax done with ex2)
#define SCALE_Q 0.18033688011112042f

// ---------------- scratch (__device__ globals; no cudaMalloc allowed) -------
__device__ __half g_qh[S_LEN * NH * HD];     // [2048][1024] fp16 (pre-scaled)
__device__ __half g_kh[S_LEN * NKV * HD];    // [2048][256]  fp16
__device__ __half g_vh[S_LEN * NKV * HD];    // [2048][256]  fp16
__device__ float g_opart[NKV][S_LEN * NH * HD];   // per-kv attention partials
__device__ float g_o[S_LEN * NH * HD];            // reduced attention output

__device__ __forceinline__ float ex2f(float x) {
    float y; asm("ex2.approx.ftz.f32 %0, %1;" : "=f"(y) : "f"(x)); return y;
}
__device__ __forceinline__ uint32_t smem_u32(const void* p) {
    uint32_t a;
    asm("{ .reg .u64 t; cvta.to.shared.u64 t, %1; cvt.u32.u64 %0, t; }"
        : "=r"(a) : "l"(p));
    return a;
}

// m16n8k16 fp16 MMA, fp32 accumulate: C += A x B
__device__ __forceinline__ void mma16816(float* c, const uint32_t* a,
                                         uint32_t b0, uint32_t b1) {
    asm volatile(
        "mma.sync.aligned.m16n8k16.row.col.f32.f16.f16.f32 "
        "{%0,%1,%2,%3}, {%4,%5,%6,%7}, {%8,%9}, {%0,%1,%2,%3};"
        : "+f"(c[0]), "+f"(c[1]), "+f"(c[2]), "+f"(c[3])
        : "r"(a[0]), "r"(a[1]), "r"(a[2]), "r"(a[3]), "r"(b0), "r"(b1));
}

__device__ __forceinline__ void ldsm_x4(uint32_t& a, uint32_t& b, uint32_t& c,
                                        uint32_t& d, uint32_t addr) {
    asm volatile("ldmatrix.sync.aligned.m8n8.x4.shared.b16 {%0,%1,%2,%3}, [%4];"
                 : "=r"(a), "=r"(b), "=r"(c), "=r"(d) : "r"(addr));
}
__device__ __forceinline__ void ldsm_x4_t(uint32_t& a, uint32_t& b, uint32_t& c,
                                          uint32_t& d, uint32_t addr) {
    asm volatile("ldmatrix.sync.aligned.m8n8.x4.trans.shared.b16 {%0,%1,%2,%3}, [%4];"
                 : "=r"(a), "=r"(b), "=r"(c), "=r"(d) : "r"(addr));
}

__device__ __forceinline__ uint32_t packh2(float a, float b) {
    __half2 h = __floats2half2_rn(a, b);
    return *(uint32_t*)&h;
}

// ---------------------------------------------------------------------------
// fp32 GEMM body: 32x64 tile, 128 threads, 4x4 micro-tile.
// C[m0+i][j] = sum_k A[m0+i][k] * Bn[j][k]
// ---------------------------------------------------------------------------
struct QkvEpi {
    __half* Cb; int ldc; float scale;
    __device__ __forceinline__ void operator()(float (&acc)[4][4], int row, int col) const {
        #pragma unroll
        for (int i = 0; i < 4; i++) {
            uint2 u = { packh2(acc[i][0] * scale, acc[i][1] * scale),
                        packh2(acc[i][2] * scale, acc[i][3] * scale) };
            *(uint2*)&Cb[(size_t)(row + i) * ldc + col] = u;
        }
    }
};
struct OutEpi {
    float* outb;
    __device__ __forceinline__ void operator()(float (&acc)[4][4], int row, int col) const {
        #pragma unroll
        for (int i = 0; i < 4; i++) {
            float4 o4 = {acc[i][0], acc[i][1], acc[i][2], acc[i][3]};
            *(float4*)&outb[(size_t)(row + i) * OUT_DIM + col] = o4;
        }
    }
};

template <typename EPI>
__device__ __forceinline__ void gemm_body(
    const float* __restrict__ A, const float* __restrict__ Bn,
    int K, int m0, EPI epi)
{
    __shared__ float As[16][36];
    __shared__ float Bs[16][68];
    const int tid = threadIdx.x;
    const int tx = tid & 15, ty = tid >> 4;       // 16 x 8
    const int r0 = ty * 4, c0 = tx * 4;           // 32 rows, 64 cols
    const int kk = tid & 15, rb = tid >> 4;       // stager coords

    float acc[4][4] = {};
    for (int k0 = 0; k0 < K; k0 += 16) {
        #pragma unroll
        for (int rep = 0; rep < 4; rep++) {
            int i = rb + rep * 8;
            As[kk][i] = A[(size_t)(m0 + i) * K + k0 + kk];
        }
        #pragma unroll
        for (int rep = 0; rep < 8; rep++) {
            int i = rb + rep * 8;
            Bs[kk][i] = Bn[(size_t)i * K + k0 + kk];
        }
        __syncthreads();
        #pragma unroll
        for (int ks = 0; ks < 16; ks++) {
            float4 a4 = *(const float4*)&As[ks][r0];
            float4 b4 = *(const float4*)&Bs[ks][c0];
            float av[4] = {a4.x, a4.y, a4.z, a4.w};
            float bv[4] = {b4.x, b4.y, b4.z, b4.w};
            #pragma unroll
            for (int i = 0; i < 4; i++)
                #pragma unroll
                for (int j = 0; j < 4; j++)
                    acc[i][j] += av[i] * bv[j];
        }
        __syncthreads();
    }
    epi(acc, m0 + r0, c0);
}

// QKV projection -> fp16 outputs. grid (64, 24): 64 M-tiles of 32 rows.
__global__ __launch_bounds__(128)
void qkv_kernel(const float* __restrict__ x,
                const float* __restrict__ wq,
                const float* __restrict__ wk,
                const float* __restrict__ wv)
{
    const int by = blockIdx.y;
    const float* B; __half* C; int ldc, coff; float scale;
    if (by < 16)      { B = wq; C = g_qh; ldc = NH * HD;  coff = by * 64;        scale = SCALE_Q; }
    else if (by < 20) { B = wk; C = g_kh; ldc = NKV * HD; coff = (by - 16) * 64; scale = 1.0f; }
    else              { B = wv; C = g_vh; ldc = NKV * HD; coff = (by - 20) * 64; scale = 1.0f; }
    QkvEpi epi = { C + coff, ldc, scale };
    gemm_body(x, B + (size_t)coff * IN_DIM, IN_DIM, blockIdx.x * 32, epi);
}

// Output projection: out = g_o[2048,1024] @ Wo^T. grid (64, 8) = 512 CTAs.
__global__ __launch_bounds__(128)
void out_gemm_kernel(const float* __restrict__ wo, float* __restrict__ out)
{
    const int n0 = blockIdx.y * 64;
    OutEpi epi = { out + n0 };
    gemm_body(g_o, wo + (size_t)n0 * (NH * HD), NH * HD, blockIdx.x * 32, epi);
}

// Sum kv partials. grid 2048 x 256 (float4 per thread).
__global__ __launch_bounds__(256)
void reduce_o_kernel()
{
    int i = blockIdx.x * 256 + threadIdx.x;
    const float4* p0 = (const float4*)g_opart[0];
    const float4* p1 = (const float4*)g_opart[1];
    const float4* p2 = (const float4*)g_opart[2];
    const float4* p3 = (const float4*)g_opart[3];
    float4 a = p0[i], b = p1[i], c = p2[i], d = p3[i];
    float4 r = { a.x + b.x + c.x + d.x, a.y + b.y + c.y + d.y,
                 a.z + b.z + c.z + d.z, a.w + b.w + c.w + d.w };
    ((float4*)g_o)[i] = r;
}

// ---------------------------------------------------------------------------
// mma.sync flash attention with ldmatrix fragment loads.
// grid (32 s-blocks heavy-first, 16 h, 4 kv), 128 threads (4 warps x 16 rows).
// sK[key][d], sV[key][d] both row-major, pitch 72 halves (conflict-free LDSM).
// ---------------------------------------------------------------------------
#define KP 72

__global__ __launch_bounds__(128)
void attn_kernel()
{
    __shared__ __align__(16) __half sK[64 * KP];
    __shared__ __align__(16) __half sV[64 * KP];

    const int tid = threadIdx.x;
    const int w   = tid >> 5;
    const int l   = tid & 31;
    const int lr  = l >> 2;          // fragment row (0..7)
    const int lc  = l & 3;           // fragment col pair (0..3)
    const int bs  = 31 - (int)blockIdx.x;   // heavy blocks first
    const int h   = blockIdx.y;
    const int kv  = blockIdx.z;
    const int s0  = bs * 64;
    const int T   = bs + 1;

    // ---- Q A-fragments, loaded once ---------------------------------------
    uint32_t qf[4][4];
    {
        const __half* qb = g_qh + (size_t)(s0 + w * 16) * (NH * HD) + h * HD;
        #pragma unroll
        for (int ks = 0; ks < 4; ks++) {
            int k0 = ks * 16 + lc * 2;
            qf[ks][0] = *(const uint32_t*)(qb + (size_t)lr * (NH * HD) + k0);
            qf[ks][1] = *(const uint32_t*)(qb + (size_t)(lr + 8) * (NH * HD) + k0);
            qf[ks][2] = *(const uint32_t*)(qb + (size_t)lr * (NH * HD) + k0 + 8);
            qf[ks][3] = *(const uint32_t*)(qb + (size_t)(lr + 8) * (NH * HD) + k0 + 8);
        }
    }

    // ---- per-lane ldmatrix base addresses ---------------------------------
    const int g8 = l >> 3, r8 = l & 7;
    // QK (non-trans): matrix g: rows key0+(g>>1)*8+r8, cols d0+(g&1)*8
    const uint32_t aK = smem_u32(sK) +
        (((g8 >> 1) * 8 + r8) * KP + (g8 & 1) * 8) * 2;
    // PV (trans): matrix g: rows key0+(g&1)*8+r8, cols d0+(g>>1)*8
    const uint32_t aV = smem_u32(sV) +
        (((g8 & 1) * 8 + r8) * KP + (g8 >> 1) * 8) * 2;

    float oacc[8][4] = {};
    float lsum0 = 0.f, lsum1 = 0.f;
    const int row0 = s0 + w * 16 + lr;
    const int row1 = row0 + 8;

    const int key = tid >> 1, hf = tid & 1;
    const __half* kbase = g_kh + (size_t)key * (NKV * HD) + kv * HD + hf * 32;
    const __half* vbase = g_vh + (size_t)key * (NKV * HD) + kv * HD + hf * 32;
    uint4* dK = (uint4*)(sK + key * KP + hf * 32);
    uint4* dV = (uint4*)(sV + key * KP + hf * 32);

    for (int t = 0; t < T; t++) {
        __syncthreads();   // prior tile's smem reads complete

        // ---- load K,V tiles [64 keys][64 d] row-major ---------------------
        {
            const uint4* sk4 = (const uint4*)(kbase + (size_t)t * 64 * (NKV * HD));
            const uint4* sv4 = (const uint4*)(vbase + (size_t)t * 64 * (NKV * HD));
            dK[0] = sk4[0]; dK[1] = sk4[1]; dK[2] = sk4[2]; dK[3] = sk4[3];
            dV[0] = sv4[0]; dV[1] = sv4[1]; dV[2] = sv4[2]; dV[3] = sv4[3];
        }
        __syncthreads();

        // ---- S = Q K^T ----------------------------------------------------
        float sc[8][4] = {};
        #pragma unroll
        for (int ks = 0; ks < 4; ks++) {
            #pragma unroll
            for (int kg = 0; kg < 4; kg++) {
                uint32_t b0, b1, b2, b3;
                ldsm_x4(b0, b1, b2, b3, aK + (kg * 16 * KP + ks * 16) * 2);
                mma16816(sc[2 * kg],     qf[ks], b0, b1);
                mma16816(sc[2 * kg + 1], qf[ks], b2, b3);
            }
        }

        // ---- mask + exp (un-normalized) + repack as PV A-frags ------------
        uint32_t pf[4][4];
        const int jb = t * 64;
        #pragma unroll
        for (int nf = 0; nf < 8; nf++) {
            int j0 = jb + nf * 8 + lc * 2;
            float p00 = (j0     <= row0) ? ex2f(sc[nf][0]) : 0.f;
            float p01 = (j0 + 1 <= row0) ? ex2f(sc[nf][1]) : 0.f;
            float p10 = (j0     <= row1) ? ex2f(sc[nf][2]) : 0.f;
            float p11 = (j0 + 1 <= row1) ? ex2f(sc[nf][3]) : 0.f;
            lsum0 += p00 + p01;
            lsum1 += p10 + p11;
            pf[nf >> 1][(nf & 1) * 2 + 0] = packh2(p00, p01);
            pf[nf >> 1][(nf & 1) * 2 + 1] = packh2(p10, p11);
        }

        // ---- O += P V -----------------------------------------------------
        #pragma unroll
        for (int ksg = 0; ksg < 4; ksg++) {
            #pragma unroll
            for (int nfp = 0; nfp < 4; nfp++) {
                uint32_t b0, b1, b2, b3;
                ldsm_x4_t(b0, b1, b2, b3, aV + (ksg * 16 * KP + nfp * 16) * 2);
                mma16816(oacc[2 * nfp],     pf[ksg], b0, b1);
                mma16816(oacc[2 * nfp + 1], pf[ksg], b2, b3);
            }
        }
    }

    // ---- row-sum reduction across 4 lanes sharing each row -----------------
    lsum0 += __shfl_xor_sync(0xffffffffu, lsum0, 1);
    lsum0 += __shfl_xor_sync(0xffffffffu, lsum0, 2);
    lsum1 += __shfl_xor_sync(0xffffffffu, lsum1, 1);
    lsum1 += __shfl_xor_sync(0xffffffffu, lsum1, 2);
    const float inv0 = 0.25f / lsum0;
    const float inv1 = 0.25f / lsum1;

    // ---- store per-kv partial O -------------------------------------------
    float* d0 = g_opart[kv] + (size_t)row0 * (NH * HD) + h * HD + lc * 2;
    float* d1 = g_opart[kv] + (size_t)row1 * (NH * HD) + h * HD + lc * 2;
    #pragma unroll
    for (int df = 0; df < 8; df++) {
        float2 u0 = { oacc[df][0] * inv0, oacc[df][1] * inv0 };
        float2 u1 = { oacc[df][2] * inv1, oacc[df][3] * inv1 };
        *(float2*)(d0 + df * 8) = u0;
        *(float2*)(d1 + df * 8) = u1;
    }
}

// ---------------------------------------------------------------------------
extern "C" void kernel_launch(void* const* d_in, const int* in_sizes, int n_in,
                              void* d_out, int out_size)
{
    const float* x  = (const float*)d_in[0];
    const float* Wq = (const float*)d_in[1];
    const float* Wk = (const float*)d_in[2];
    const float* Wv = (const float*)d_in[3];
    const float* Wo = (const float*)d_in[4];
    float* out = (float*)d_out;

    qkv_kernel<<<dim3(64, 24), 128>>>(x, Wq, Wk, Wv);
    attn_kernel<<<dim3(32, 16, 4), 128>>>();
    reduce_o_kernel<<<2048, 256>>>();
    out_gemm_kernel<<<dim3(64, 8), 128>>>(Wo, out);
}

// round 8
// speedup vs baseline: 6.2174x; 1.5258x over previous
#include <cuda_runtime.h>
#include <cuda_fp16.h>
#include <cstdint>

#define S_LEN   2048
#define IN_DIM  512
#define OUT_DIM 512
#define NH      16
#define NKV     4
#define HD      64

// Q pre-scale: 1/sqrt(64) * log2(e)  (softmax done with ex2); folded into Wq.
#define SCALE_Q 0.18033688011112042f

// ---------------- scratch (__device__ globals; no cudaMalloc allowed) -------
__device__ __half g_xh[S_LEN * IN_DIM];            // x in fp16
__device__ __half g_wh[(NH * HD + 2 * NKV * HD) * IN_DIM];  // [Wq*s | Wk | Wv] fp16
__device__ __half g_woh[OUT_DIM * NH * HD];        // Wo fp16
__device__ __half g_qh[S_LEN * NH * HD];           // q fp16 (pre-scaled)
__device__ __half g_kh[S_LEN * NKV * HD];          // k fp16
__device__ __half g_vh[S_LEN * NKV * HD];          // v fp16
__device__ float g_opart[NKV][S_LEN * NH * HD];    // per-kv attention partials
__device__ __half g_oh[S_LEN * NH * HD];           // reduced attention output fp16

__device__ __forceinline__ float ex2f(float x) {
    float y; asm("ex2.approx.ftz.f32 %0, %1;" : "=f"(y) : "f"(x)); return y;
}
__device__ __forceinline__ uint32_t smem_u32(const void* p) {
    uint32_t a;
    asm("{ .reg .u64 t; cvta.to.shared.u64 t, %1; cvt.u32.u64 %0, t; }"
        : "=r"(a) : "l"(p));
    return a;
}

// m16n8k16 fp16 MMA, fp32 accumulate: C += A x B
__device__ __forceinline__ void mma16816(float* c, const uint32_t* a,
                                         uint32_t b0, uint32_t b1) {
    asm volatile(
        "mma.sync.aligned.m16n8k16.row.col.f32.f16.f16.f32 "
        "{%0,%1,%2,%3}, {%4,%5,%6,%7}, {%8,%9}, {%0,%1,%2,%3};"
        : "+f"(c[0]), "+f"(c[1]), "+f"(c[2]), "+f"(c[3])
        : "r"(a[0]), "r"(a[1]), "r"(a[2]), "r"(a[3]), "r"(b0), "r"(b1));
}
__device__ __forceinline__ void ldsm_x4(uint32_t& a, uint32_t& b, uint32_t& c,
                                        uint32_t& d, uint32_t addr) {
    asm volatile("ldmatrix.sync.aligned.m8n8.x4.shared.b16 {%0,%1,%2,%3}, [%4];"
                 : "=r"(a), "=r"(b), "=r"(c), "=r"(d) : "r"(addr));
}
__device__ __forceinline__ void ldsm_x4_t(uint32_t& a, uint32_t& b, uint32_t& c,
                                          uint32_t& d, uint32_t addr) {
    asm volatile("ldmatrix.sync.aligned.m8n8.x4.trans.shared.b16 {%0,%1,%2,%3}, [%4];"
                 : "=r"(a), "=r"(b), "=r"(c), "=r"(d) : "r"(addr));
}
__device__ __forceinline__ uint32_t packh2(float a, float b) {
    __half2 h = __floats2half2_rn(a, b);
    return *(uint32_t*)&h;
}

// ---------------------------------------------------------------------------
// fp32 -> fp16 convert (dst selected by tag; device-global addresses are not
// visible to host code). 4 elements / thread.
// ---------------------------------------------------------------------------
__global__ __launch_bounds__(256)
void f2h_kernel(const float* __restrict__ src, int which, int n4, float scale)
{
    __half* dst;
    if (which == 0)      dst = g_xh;
    else if (which == 1) dst = g_wh;
    else if (which == 2) dst = g_wh + (NH * HD) * IN_DIM;
    else if (which == 3) dst = g_wh + (NH * HD + NKV * HD) * IN_DIM;
    else                 dst = g_woh;
    int i = blockIdx.x * 256 + threadIdx.x;
    if (i < n4) {
        float4 v = ((const float4*)src)[i];
        uint2 u = { packh2(v.x * scale, v.y * scale),
                    packh2(v.z * scale, v.w * scale) };
        ((uint2*)dst)[i] = u;
    }
}

// ---------------------------------------------------------------------------
// fp16 tensor-core GEMM body: C[m0+..][..] = A[M,K] @ Bn[Ntile,K]^T.
// 128 threads / 4 warps; warp w covers 16 rows. K consumed in 64-wide chunks.
// NF = number of 8-col n-fragments (NF=8 -> Ntile 64, NF=4 -> Ntile 32).
// ---------------------------------------------------------------------------
struct HEpiQkv {
    __half* C; int ldc;
    template <int NF>
    __device__ __forceinline__ void operator()(float (&acc)[NF][4], int row0, int lc) const {
        #pragma unroll
        for (int nf = 0; nf < NF; nf++) {
            int col = nf * 8 + lc * 2;
            *(uint32_t*)&C[(size_t)row0 * ldc + col]       = packh2(acc[nf][0], acc[nf][1]);
            *(uint32_t*)&C[(size_t)(row0 + 8) * ldc + col] = packh2(acc[nf][2], acc[nf][3]);
        }
    }
};
struct HEpiOut {
    float* C;
    template <int NF>
    __device__ __forceinline__ void operator()(float (&acc)[NF][4], int row0, int lc) const {
        #pragma unroll
        for (int nf = 0; nf < NF; nf++) {
            int col = nf * 8 + lc * 2;
            float2 u0 = { acc[nf][0], acc[nf][1] };
            float2 u1 = { acc[nf][2], acc[nf][3] };
            *(float2*)&C[(size_t)row0 * OUT_DIM + col]       = u0;
            *(float2*)&C[(size_t)(row0 + 8) * OUT_DIM + col] = u1;
        }
    }
};

template <int NF, class EPI>
__device__ __forceinline__ void hgemm_body(
    const __half* __restrict__ A, const __half* __restrict__ Bn,
    int K, int m0, EPI epi)
{
    __shared__ __align__(16) __half sA[64 * 72];
    __shared__ __align__(16) __half sB[NF * 8 * 72];
    const int tid = threadIdx.x;
    const int w = tid >> 5, l = tid & 31;
    const int g8 = l >> 3, r8 = l & 7;
    const int lr = l >> 2, lc = l & 3;

    // A-frag ldsm: matrices = (rows +0/+8) x (cols +0/+8) quadrants
    const uint32_t aA = smem_u32(sA) +
        ((w * 16 + (g8 & 1) * 8 + r8) * 72 + (g8 >> 1) * 8) * 2;
    // B-frag ldsm (same pattern as attn QK, proven correct)
    const uint32_t aB = smem_u32(sB) +
        (((g8 >> 1) * 8 + r8) * 72 + (g8 & 1) * 8) * 2;

    float acc[NF][4] = {};

    const int nch = K >> 6;
    for (int kc = 0; kc < nch; kc++) {
        if (kc) __syncthreads();
        #pragma unroll
        for (int j = 0; j < 4; j++) {          // A: 512 uint4, 4/thread
            int u = tid * 4 + j;
            int row = u >> 3, c8 = u & 7;
            *(uint4*)(sA + row * 72 + c8 * 8) =
                *(const uint4*)(A + (size_t)(m0 + row) * K + kc * 64 + c8 * 8);
        }
        constexpr int PB = NF * 64 / 128;      // B: NF*64 uint4
        #pragma unroll
        for (int j = 0; j < PB; j++) {
            int u = tid * PB + j;
            int row = u >> 3, c8 = u & 7;
            *(uint4*)(sB + row * 72 + c8 * 8) =
                *(const uint4*)(Bn + (size_t)row * K + kc * 64 + c8 * 8);
        }
        __syncthreads();

        #pragma unroll
        for (int ks = 0; ks < 4; ks++) {
            uint32_t af[4];
            ldsm_x4(af[0], af[1], af[2], af[3], aA + ks * 16 * 2);
            #pragma unroll
            for (int ng = 0; ng < NF / 2; ng++) {
                uint32_t b0, b1, b2, b3;
                ldsm_x4(b0, b1, b2, b3, aB + (ng * 16 * 72 + ks * 16) * 2);
                mma16816(acc[2 * ng],     af, b0, b1);
                mma16816(acc[2 * ng + 1], af, b2, b3);
            }
        }
    }
    epi(acc, m0 + w * 16 + lr, lc);
}

// QKV projection (fp16 HMMA). grid (32, 24).
__global__ __launch_bounds__(128)
void qkv_kernel()
{
    const int by = blockIdx.y;
    const __half* Bn; __half* C; int ldc;
    if (by < 16) {
        Bn = g_wh + (size_t)(by * 64) * IN_DIM;
        C = g_qh + by * 64; ldc = NH * HD;
    } else if (by < 20) {
        Bn = g_wh + (size_t)(NH * HD + (by - 16) * 64) * IN_DIM;
        C = g_kh + (by - 16) * 64; ldc = NKV * HD;
    } else {
        Bn = g_wh + (size_t)(NH * HD + NKV * HD + (by - 20) * 64) * IN_DIM;
        C = g_vh + (by - 20) * 64; ldc = NKV * HD;
    }
    HEpiQkv epi = { C, ldc };
    hgemm_body<8>(g_xh, Bn, IN_DIM, blockIdx.x * 64, epi);
}

// Output projection (fp16 HMMA): out = g_oh[2048,1024] @ Wo^T. grid (32, 16).
__global__ __launch_bounds__(128)
void out_gemm_kernel(float* __restrict__ out)
{
    const int n0 = blockIdx.y * 32;
    HEpiOut epi = { out + n0 };
    hgemm_body<4>(g_oh, g_woh + (size_t)n0 * (NH * HD), NH * HD, blockIdx.x * 64, epi);
}

// Sum kv partials -> fp16 g_oh. 8 floats / thread. grid 1024 x 256.
__global__ __launch_bounds__(256)
void reduce_o_kernel()
{
    int i = blockIdx.x * 256 + threadIdx.x;
    const float4* p0 = (const float4*)g_opart[0];
    const float4* p1 = (const float4*)g_opart[1];
    const float4* p2 = (const float4*)g_opart[2];
    const float4* p3 = (const float4*)g_opart[3];
    float4 a, b, r[2];
    #pragma unroll
    for (int j = 0; j < 2; j++) {
        int k = 2 * i + j;
        a = p0[k]; b = p1[k];
        r[j].x = a.x + b.x; r[j].y = a.y + b.y; r[j].z = a.z + b.z; r[j].w = a.w + b.w;
        a = p2[k]; b = p3[k];
        r[j].x += a.x + b.x; r[j].y += a.y + b.y; r[j].z += a.z + b.z; r[j].w += a.w + b.w;
    }
    uint4 u = { packh2(r[0].x, r[0].y), packh2(r[0].z, r[0].w),
                packh2(r[1].x, r[1].y), packh2(r[1].z, r[1].w) };
    ((uint4*)g_oh)[i] = u;
}

// ---------------------------------------------------------------------------
// mma.sync flash attention with ldmatrix fragment loads (unchanged from R7).
// grid (32 s-blocks heavy-first, 16 h, 4 kv), 128 threads.
// ---------------------------------------------------------------------------
#define KP 72

__global__ __launch_bounds__(128)
void attn_kernel()
{
    __shared__ __align__(16) __half sK[64 * KP];
    __shared__ __align__(16) __half sV[64 * KP];

    const int tid = threadIdx.x;
    const int w   = tid >> 5;
    const int l   = tid & 31;
    const int lr  = l >> 2;
    const int lc  = l & 3;
    const int bs  = 31 - (int)blockIdx.x;
    const int h   = blockIdx.y;
    const int kv  = blockIdx.z;
    const int s0  = bs * 64;
    const int T   = bs + 1;

    uint32_t qf[4][4];
    {
        const __half* qb = g_qh + (size_t)(s0 + w * 16) * (NH * HD) + h * HD;
        #pragma unroll
        for (int ks = 0; ks < 4; ks++) {
            int k0 = ks * 16 + lc * 2;
            qf[ks][0] = *(const uint32_t*)(qb + (size_t)lr * (NH * HD) + k0);
            qf[ks][1] = *(const uint32_t*)(qb + (size_t)(lr + 8) * (NH * HD) + k0);
            qf[ks][2] = *(const uint32_t*)(qb + (size_t)lr * (NH * HD) + k0 + 8);
            qf[ks][3] = *(const uint32_t*)(qb + (size_t)(lr + 8) * (NH * HD) + k0 + 8);
        }
    }

    const int g8 = l >> 3, r8 = l & 7;
    const uint32_t aK = smem_u32(sK) +
        (((g8 >> 1) * 8 + r8) * KP + (g8 & 1) * 8) * 2;
    const uint32_t aV = smem_u32(sV) +
        (((g8 & 1) * 8 + r8) * KP + (g8 >> 1) * 8) * 2;

    float oacc[8][4] = {};
    float lsum0 = 0.f, lsum1 = 0.f;
    const int row0 = s0 + w * 16 + lr;
    const int row1 = row0 + 8;

    const int key = tid >> 1, hf = tid & 1;
    const __half* kbase = g_kh + (size_t)key * (NKV * HD) + kv * HD + hf * 32;
    const __half* vbase = g_vh + (size_t)key * (NKV * HD) + kv * HD + hf * 32;
    uint4* dK = (uint4*)(sK + key * KP + hf * 32);
    uint4* dV = (uint4*)(sV + key * KP + hf * 32);

    for (int t = 0; t < T; t++) {
        __syncthreads();
        {
            const uint4* sk4 = (const uint4*)(kbase + (size_t)t * 64 * (NKV * HD));
            const uint4* sv4 = (const uint4*)(vbase + (size_t)t * 64 * (NKV * HD));
            dK[0] = sk4[0]; dK[1] = sk4[1]; dK[2] = sk4[2]; dK[3] = sk4[3];
            dV[0] = sv4[0]; dV[1] = sv4[1]; dV[2] = sv4[2]; dV[3] = sv4[3];
        }
        __syncthreads();

        float sc[8][4] = {};
        #pragma unroll
        for (int ks = 0; ks < 4; ks++) {
            #pragma unroll
            for (int kg = 0; kg < 4; kg++) {
                uint32_t b0, b1, b2, b3;
                ldsm_x4(b0, b1, b2, b3, aK + (kg * 16 * KP + ks * 16) * 2);
                mma16816(sc[2 * kg],     qf[ks], b0, b1);
                mma16816(sc[2 * kg + 1], qf[ks], b2, b3);
            }
        }

        uint32_t pf[4][4];
        const int jb = t * 64;
        #pragma unroll
        for (int nf = 0; nf < 8; nf++) {
            int j0 = jb + nf * 8 + lc * 2;
            float p00 = (j0     <= row0) ? ex2f(sc[nf][0]) : 0.f;
            float p01 = (j0 + 1 <= row0) ? ex2f(sc[nf][1]) : 0.f;
            float p10 = (j0     <= row1) ? ex2f(sc[nf][2]) : 0.f;
            float p11 = (j0 + 1 <= row1) ? ex2f(sc[nf][3]) : 0.f;
            lsum0 += p00 + p01;
            lsum1 += p10 + p11;
            pf[nf >> 1][(nf & 1) * 2 + 0] = packh2(p00, p01);
            pf[nf >> 1][(nf & 1) * 2 + 1] = packh2(p10, p11);
        }

        #pragma unroll
        for (int ksg = 0; ksg < 4; ksg++) {
            #pragma unroll
            for (int nfp = 0; nfp < 4; nfp++) {
                uint32_t b0, b1, b2, b3;
                ldsm_x4_t(b0, b1, b2, b3, aV + (ksg * 16 * KP + nfp * 16) * 2);
                mma16816(oacc[2 * nfp],     pf[ksg], b0, b1);
                mma16816(oacc[2 * nfp + 1], pf[ksg], b2, b3);
            }
        }
    }

    lsum0 += __shfl_xor_sync(0xffffffffu, lsum0, 1);
    lsum0 += __shfl_xor_sync(0xffffffffu, lsum0, 2);
    lsum1 += __shfl_xor_sync(0xffffffffu, lsum1, 1);
    lsum1 += __shfl_xor_sync(0xffffffffu, lsum1, 2);
    const float inv0 = 0.25f / lsum0;
    const float inv1 = 0.25f / lsum1;

    float* d0 = g_opart[kv] + (size_t)row0 * (NH * HD) + h * HD + lc * 2;
    float* d1 = g_opart[kv] + (size_t)row1 * (NH * HD) + h * HD + lc * 2;
    #pragma unroll
    for (int df = 0; df < 8; df++) {
        float2 u0 = { oacc[df][0] * inv0, oacc[df][1] * inv0 };
        float2 u1 = { oacc[df][2] * inv1, oacc[df][3] * inv1 };
        *(float2*)(d0 + df * 8) = u0;
        *(float2*)(d1 + df * 8) = u1;
    }
}

// ---------------------------------------------------------------------------
extern "C" void kernel_launch(void* const* d_in, const int* in_sizes, int n_in,
                              void* d_out, int out_size)
{
    const float* x  = (const float*)d_in[0];
    const float* Wq = (const float*)d_in[1];
    const float* Wk = (const float*)d_in[2];
    const float* Wv = (const float*)d_in[3];
    const float* Wo = (const float*)d_in[4];
    float* out = (float*)d_out;

    f2h_kernel<<<1024, 256>>>(x,  0, S_LEN * IN_DIM / 4, 1.0f);
    f2h_kernel<<< 512, 256>>>(Wq, 1, NH * HD * IN_DIM / 4, SCALE_Q);
    f2h_kernel<<< 128, 256>>>(Wk, 2, NKV * HD * IN_DIM / 4, 1.0f);
    f2h_kernel<<< 128, 256>>>(Wv, 3, NKV * HD * IN_DIM / 4, 1.0f);
    f2h_kernel<<< 512, 256>>>(Wo, 4, OUT_DIM * NH * HD / 4, 1.0f);

    qkv_kernel<<<dim3(32, 24), 128>>>();
    attn_kernel<<<dim3(32, 16, 4), 128>>>();
    reduce_o_kernel<<<1024, 256>>>();
    out_gemm_kernel<<<dim3(32, 16), 128>>>(out);
}

// round 9
// speedup vs baseline: 6.4913x; 1.0440x over previous
#include <cuda_runtime.h>
#include <cuda_fp16.h>
#include <cstdint>

#define S_LEN   2048
#define IN_DIM  512
#define OUT_DIM 512
#define NH      16
#define NKV     4
#define HD      64

// Q pre-scale: 1/sqrt(64) * log2(e)  (softmax done with ex2); folded into Wq.
#define SCALE_Q 0.18033688011112042f

// ---------------- scratch (__device__ globals; no cudaMalloc allowed) -------
__device__ __half g_xh[S_LEN * IN_DIM];            // x in fp16
__device__ __half g_wh[(NH * HD + 2 * NKV * HD) * IN_DIM];  // [Wq*s | Wk | Wv] fp16
__device__ __half g_woh[OUT_DIM * NH * HD];        // Wo fp16
__device__ __half g_qh[S_LEN * NH * HD];           // q fp16 (pre-scaled)
__device__ __half g_kh[S_LEN * NKV * HD];          // k fp16
__device__ __half g_vh[S_LEN * NKV * HD];          // v fp16
__device__ float g_opart[NKV][S_LEN * NH * HD];    // per-kv attention partials
__device__ __half g_oh[S_LEN * NH * HD];           // reduced attention output fp16

__device__ __forceinline__ float ex2f(float x) {
    float y; asm("ex2.approx.ftz.f32 %0, %1;" : "=f"(y) : "f"(x)); return y;
}
__device__ __forceinline__ uint32_t smem_u32(const void* p) {
    uint32_t a;
    asm("{ .reg .u64 t; cvta.to.shared.u64 t, %1; cvt.u32.u64 %0, t; }"
        : "=r"(a) : "l"(p));
    return a;
}

// m16n8k16 fp16 MMA, fp32 accumulate: C += A x B
__device__ __forceinline__ void mma16816(float* c, const uint32_t* a,
                                         uint32_t b0, uint32_t b1) {
    asm volatile(
        "mma.sync.aligned.m16n8k16.row.col.f32.f16.f16.f32 "
        "{%0,%1,%2,%3}, {%4,%5,%6,%7}, {%8,%9}, {%0,%1,%2,%3};"
        : "+f"(c[0]), "+f"(c[1]), "+f"(c[2]), "+f"(c[3])
        : "r"(a[0]), "r"(a[1]), "r"(a[2]), "r"(a[3]), "r"(b0), "r"(b1));
}
__device__ __forceinline__ void ldsm_x4(uint32_t& a, uint32_t& b, uint32_t& c,
                                        uint32_t& d, uint32_t addr) {
    asm volatile("ldmatrix.sync.aligned.m8n8.x4.shared.b16 {%0,%1,%2,%3}, [%4];"
                 : "=r"(a), "=r"(b), "=r"(c), "=r"(d) : "r"(addr));
}
__device__ __forceinline__ void ldsm_x4_t(uint32_t& a, uint32_t& b, uint32_t& c,
                                          uint32_t& d, uint32_t addr) {
    asm volatile("ldmatrix.sync.aligned.m8n8.x4.trans.shared.b16 {%0,%1,%2,%3}, [%4];"
                 : "=r"(a), "=r"(b), "=r"(c), "=r"(d) : "r"(addr));
}
__device__ __forceinline__ uint32_t packh2(float a, float b) {
    __half2 h = __floats2half2_rn(a, b);
    return *(uint32_t*)&h;
}

// ---------------------------------------------------------------------------
// Fused fp32 -> fp16 convert for all 5 tensors. One float4 per thread.
// Segment boundaries are block-aligned (256 float4 per block).
//   blocks [0,1024)      : x   (262144 f4)
//   blocks [1024,1536)   : Wq  (131072 f4, scaled)
//   blocks [1536,1664)   : Wk  (32768 f4)
//   blocks [1664,1792)   : Wv  (32768 f4)
//   blocks [1792,2304)   : Wo  (131072 f4)
// ---------------------------------------------------------------------------
__global__ __launch_bounds__(256)
void f2h_all_kernel(const float* __restrict__ x,  const float* __restrict__ wq,
                    const float* __restrict__ wk, const float* __restrict__ wv,
                    const float* __restrict__ wo)
{
    const int b = blockIdx.x;
    const float* src; __half* dst; int i; float scale = 1.0f;
    if (b < 1024)      { src = x;  dst = g_xh;  i = b * 256; }
    else if (b < 1536) { src = wq; dst = g_wh;  i = (b - 1024) * 256; scale = SCALE_Q; }
    else if (b < 1664) { src = wk; dst = g_wh + (NH * HD) * IN_DIM;            i = (b - 1536) * 256; }
    else if (b < 1792) { src = wv; dst = g_wh + (NH * HD + NKV * HD) * IN_DIM; i = (b - 1664) * 256; }
    else               { src = wo; dst = g_woh; i = (b - 1792) * 256; }
    i += threadIdx.x;
    float4 v = ((const float4*)src)[i];
    uint2 u = { packh2(v.x * scale, v.y * scale),
                packh2(v.z * scale, v.w * scale) };
    ((uint2*)dst)[i] = u;
}

// ---------------------------------------------------------------------------
// fp16 tensor-core GEMM body (unchanged from R8).
// ---------------------------------------------------------------------------
struct HEpiQkv {
    __half* C; int ldc;
    template <int NF>
    __device__ __forceinline__ void operator()(float (&acc)[NF][4], int row0, int lc) const {
        #pragma unroll
        for (int nf = 0; nf < NF; nf++) {
            int col = nf * 8 + lc * 2;
            *(uint32_t*)&C[(size_t)row0 * ldc + col]       = packh2(acc[nf][0], acc[nf][1]);
            *(uint32_t*)&C[(size_t)(row0 + 8) * ldc + col] = packh2(acc[nf][2], acc[nf][3]);
        }
    }
};
struct HEpiOut {
    float* C;
    template <int NF>
    __device__ __forceinline__ void operator()(float (&acc)[NF][4], int row0, int lc) const {
        #pragma unroll
        for (int nf = 0; nf < NF; nf++) {
            int col = nf * 8 + lc * 2;
            float2 u0 = { acc[nf][0], acc[nf][1] };
            float2 u1 = { acc[nf][2], acc[nf][3] };
            *(float2*)&C[(size_t)row0 * OUT_DIM + col]       = u0;
            *(float2*)&C[(size_t)(row0 + 8) * OUT_DIM + col] = u1;
        }
    }
};

template <int NF, class EPI>
__device__ __forceinline__ void hgemm_body(
    const __half* __restrict__ A, const __half* __restrict__ Bn,
    int K, int m0, EPI epi)
{
    __shared__ __align__(16) __half sA[64 * 72];
    __shared__ __align__(16) __half sB[NF * 8 * 72];
    const int tid = threadIdx.x;
    const int w = tid >> 5, l = tid & 31;
    const int g8 = l >> 3, r8 = l & 7;
    const int lr = l >> 2, lc = l & 3;

    const uint32_t aA = smem_u32(sA) +
        ((w * 16 + (g8 & 1) * 8 + r8) * 72 + (g8 >> 1) * 8) * 2;
    const uint32_t aB = smem_u32(sB) +
        (((g8 >> 1) * 8 + r8) * 72 + (g8 & 1) * 8) * 2;

    float acc[NF][4] = {};

    const int nch = K >> 6;
    for (int kc = 0; kc < nch; kc++) {
        if (kc) __syncthreads();
        #pragma unroll
        for (int j = 0; j < 4; j++) {
            int u = tid * 4 + j;
            int row = u >> 3, c8 = u & 7;
            *(uint4*)(sA + row * 72 + c8 * 8) =
                *(const uint4*)(A + (size_t)(m0 + row) * K + kc * 64 + c8 * 8);
        }
        constexpr int PB = NF * 64 / 128;
        #pragma unroll
        for (int j = 0; j < PB; j++) {
            int u = tid * PB + j;
            int row = u >> 3, c8 = u & 7;
            *(uint4*)(sB + row * 72 + c8 * 8) =
                *(const uint4*)(Bn + (size_t)row * K + kc * 64 + c8 * 8);
        }
        __syncthreads();

        #pragma unroll
        for (int ks = 0; ks < 4; ks++) {
            uint32_t af[4];
            ldsm_x4(af[0], af[1], af[2], af[3], aA + ks * 16 * 2);
            #pragma unroll
            for (int ng = 0; ng < NF / 2; ng++) {
                uint32_t b0, b1, b2, b3;
                ldsm_x4(b0, b1, b2, b3, aB + (ng * 16 * 72 + ks * 16) * 2);
                mma16816(acc[2 * ng],     af, b0, b1);
                mma16816(acc[2 * ng + 1], af, b2, b3);
            }
        }
    }
    epi(acc, m0 + w * 16 + lr, lc);
}

// QKV projection (fp16 HMMA). grid (32, 24).
__global__ __launch_bounds__(128)
void qkv_kernel()
{
    const int by = blockIdx.y;
    const __half* Bn; __half* C; int ldc;
    if (by < 16) {
        Bn = g_wh + (size_t)(by * 64) * IN_DIM;
        C = g_qh + by * 64; ldc = NH * HD;
    } else if (by < 20) {
        Bn = g_wh + (size_t)(NH * HD + (by - 16) * 64) * IN_DIM;
        C = g_kh + (by - 16) * 64; ldc = NKV * HD;
    } else {
        Bn = g_wh + (size_t)(NH * HD + NKV * HD + (by - 20) * 64) * IN_DIM;
        C = g_vh + (by - 20) * 64; ldc = NKV * HD;
    }
    HEpiQkv epi = { C, ldc };
    hgemm_body<8>(g_xh, Bn, IN_DIM, blockIdx.x * 64, epi);
}

// Output projection (fp16 HMMA). grid (32, 16).
__global__ __launch_bounds__(128)
void out_gemm_kernel(float* __restrict__ out)
{
    const int n0 = blockIdx.y * 32;
    HEpiOut epi = { out + n0 };
    hgemm_body<4>(g_oh, g_woh + (size_t)n0 * (NH * HD), NH * HD, blockIdx.x * 64, epi);
}

// Sum kv partials -> fp16 g_oh. 8 floats / thread. grid 1024 x 256.
__global__ __launch_bounds__(256)
void reduce_o_kernel()
{
    int i = blockIdx.x * 256 + threadIdx.x;
    const float4* p0 = (const float4*)g_opart[0];
    const float4* p1 = (const float4*)g_opart[1];
    const float4* p2 = (const float4*)g_opart[2];
    const float4* p3 = (const float4*)g_opart[3];
    float4 a, b, r[2];
    #pragma unroll
    for (int j = 0; j < 2; j++) {
        int k = 2 * i + j;
        a = p0[k]; b = p1[k];
        r[j].x = a.x + b.x; r[j].y = a.y + b.y; r[j].z = a.z + b.z; r[j].w = a.w + b.w;
        a = p2[k]; b = p3[k];
        r[j].x += a.x + b.x; r[j].y += a.y + b.y; r[j].z += a.z + b.z; r[j].w += a.w + b.w;
    }
    uint4 u = { packh2(r[0].x, r[0].y), packh2(r[0].z, r[0].w),
                packh2(r[1].x, r[1].y), packh2(r[1].z, r[1].w) };
    ((uint4*)g_oh)[i] = u;
}

// ---------------------------------------------------------------------------
// mma.sync flash attention: double-buffered K/V smem with register prefetch,
// ONE __syncthreads per tile, mask only on the diagonal tile.
// grid (32 s-blocks heavy-first, 16 h, 4 kv), 128 threads.
// ---------------------------------------------------------------------------
#define KP 72
#define BUFB (64 * KP * 2)   // bytes per K (or V) buffer

__global__ __launch_bounds__(128)
void attn_kernel()
{
    __shared__ __align__(16) __half sK[2][64 * KP];
    __shared__ __align__(16) __half sV[2][64 * KP];

    const int tid = threadIdx.x;
    const int w   = tid >> 5;
    const int l   = tid & 31;
    const int lr  = l >> 2;
    const int lc  = l & 3;
    const int bs  = 31 - (int)blockIdx.x;   // heavy blocks first
    const int h   = blockIdx.y;
    const int kv  = blockIdx.z;
    const int s0  = bs * 64;
    const int T   = bs + 1;

    // ---- Q A-fragments, loaded once ---------------------------------------
    uint32_t qf[4][4];
    {
        const __half* qb = g_qh + (size_t)(s0 + w * 16) * (NH * HD) + h * HD;
        #pragma unroll
        for (int ks = 0; ks < 4; ks++) {
            int k0 = ks * 16 + lc * 2;
            qf[ks][0] = *(const uint32_t*)(qb + (size_t)lr * (NH * HD) + k0);
            qf[ks][1] = *(const uint32_t*)(qb + (size_t)(lr + 8) * (NH * HD) + k0);
            qf[ks][2] = *(const uint32_t*)(qb + (size_t)lr * (NH * HD) + k0 + 8);
            qf[ks][3] = *(const uint32_t*)(qb + (size_t)(lr + 8) * (NH * HD) + k0 + 8);
        }
    }

    const int g8 = l >> 3, r8 = l & 7;
    const uint32_t aK = smem_u32(sK) +
        (((g8 >> 1) * 8 + r8) * KP + (g8 & 1) * 8) * 2;
    const uint32_t aV = smem_u32(sV) +
        (((g8 & 1) * 8 + r8) * KP + (g8 >> 1) * 8) * 2;

    float oacc[8][4] = {};
    float lsum0 = 0.f, lsum1 = 0.f;
    const int row0 = s0 + w * 16 + lr;
    const int row1 = row0 + 8;

    // K/V stager: thread covers half a row (64 bytes) of each tile.
    const int key = tid >> 1, hf = tid & 1;
    const __half* kgp = g_kh + (size_t)key * (NKV * HD) + kv * HD + hf * 32;
    const __half* vgp = g_vh + (size_t)key * (NKV * HD) + kv * HD + hf * 32;
    __half* skp = &sK[0][0] + key * KP + hf * 32;
    __half* svp = &sV[0][0] + key * KP + hf * 32;

    uint4 kr[4], vr[4];
    {   // prefetch + stage tile 0 into buffer 0
        const uint4* k4 = (const uint4*)kgp;
        const uint4* v4 = (const uint4*)vgp;
        kr[0] = k4[0]; kr[1] = k4[1]; kr[2] = k4[2]; kr[3] = k4[3];
        vr[0] = v4[0]; vr[1] = v4[1]; vr[2] = v4[2]; vr[3] = v4[3];
        uint4* kd = (uint4*)skp; uint4* vd = (uint4*)svp;
        kd[0] = kr[0]; kd[1] = kr[1]; kd[2] = kr[2]; kd[3] = kr[3];
        vd[0] = vr[0]; vd[1] = vr[1]; vd[2] = vr[2]; vd[3] = vr[3];
    }
    __syncthreads();

    for (int t = 0; t < T; t++) {
        const int buf = t & 1;
        // issue next tile's LDGs now; consumed at the store below
        if (t + 1 < T) {
            const uint4* k4 = (const uint4*)(kgp + (size_t)(t + 1) * 64 * (NKV * HD));
            const uint4* v4 = (const uint4*)(vgp + (size_t)(t + 1) * 64 * (NKV * HD));
            kr[0] = k4[0]; kr[1] = k4[1]; kr[2] = k4[2]; kr[3] = k4[3];
            vr[0] = v4[0]; vr[1] = v4[1]; vr[2] = v4[2]; vr[3] = v4[3];
        }
        const uint32_t bK = aK + buf * BUFB;
        const uint32_t bV = aV + buf * BUFB;

        // ---- S = Q K^T ----------------------------------------------------
        float sc[8][4] = {};
        #pragma unroll
        for (int ks = 0; ks < 4; ks++) {
            #pragma unroll
            for (int kg = 0; kg < 4; kg++) {
                uint32_t b0, b1, b2, b3;
                ldsm_x4(b0, b1, b2, b3, bK + (kg * 16 * KP + ks * 16) * 2);
                mma16816(sc[2 * kg],     qf[ks], b0, b1);
                mma16816(sc[2 * kg + 1], qf[ks], b2, b3);
            }
        }

        // ---- exp (un-normalized); mask only on diagonal tile --------------
        uint32_t pf[4][4];
        if (t < T - 1) {
            #pragma unroll
            for (int nf = 0; nf < 8; nf++) {
                float p00 = ex2f(sc[nf][0]);
                float p01 = ex2f(sc[nf][1]);
                float p10 = ex2f(sc[nf][2]);
                float p11 = ex2f(sc[nf][3]);
                lsum0 += p00 + p01;
                lsum1 += p10 + p11;
                pf[nf >> 1][(nf & 1) * 2 + 0] = packh2(p00, p01);
                pf[nf >> 1][(nf & 1) * 2 + 1] = packh2(p10, p11);
            }
        } else {
            const int jb = t * 64;
            #pragma unroll
            for (int nf = 0; nf < 8; nf++) {
                int j0 = jb + nf * 8 + lc * 2;
                float p00 = (j0     <= row0) ? ex2f(sc[nf][0]) : 0.f;
                float p01 = (j0 + 1 <= row0) ? ex2f(sc[nf][1]) : 0.f;
                float p10 = (j0     <= row1) ? ex2f(sc[nf][2]) : 0.f;
                float p11 = (j0 + 1 <= row1) ? ex2f(sc[nf][3]) : 0.f;
                lsum0 += p00 + p01;
                lsum1 += p10 + p11;
                pf[nf >> 1][(nf & 1) * 2 + 0] = packh2(p00, p01);
                pf[nf >> 1][(nf & 1) * 2 + 1] = packh2(p10, p11);
            }
        }

        // ---- O += P V -----------------------------------------------------
        #pragma unroll
        for (int ksg = 0; ksg < 4; ksg++) {
            #pragma unroll
            for (int nfp = 0; nfp < 4; nfp++) {
                uint32_t b0, b1, b2, b3;
                ldsm_x4_t(b0, b1, b2, b3, bV + (ksg * 16 * KP + nfp * 16) * 2);
                mma16816(oacc[2 * nfp],     pf[ksg], b0, b1);
                mma16816(oacc[2 * nfp + 1], pf[ksg], b2, b3);
            }
        }

        // ---- stage next tile into the other buffer ------------------------
        if (t + 1 < T) {
            uint4* kd = (uint4*)(skp + (buf ^ 1) * 64 * KP);
            uint4* vd = (uint4*)(svp + (buf ^ 1) * 64 * KP);
            kd[0] = kr[0]; kd[1] = kr[1]; kd[2] = kr[2]; kd[3] = kr[3];
            vd[0] = vr[0]; vd[1] = vr[1]; vd[2] = vr[2]; vd[3] = vr[3];
            __syncthreads();
        }
    }

    // ---- row-sum reduction + store per-kv partial --------------------------
    lsum0 += __shfl_xor_sync(0xffffffffu, lsum0, 1);
    lsum0 += __shfl_xor_sync(0xffffffffu, lsum0, 2);
    lsum1 += __shfl_xor_sync(0xffffffffu, lsum1, 1);
    lsum1 += __shfl_xor_sync(0xffffffffu, lsum1, 2);
    const float inv0 = 0.25f / lsum0;
    const float inv1 = 0.25f / lsum1;

    float* d0 = g_opart[kv] + (size_t)row0 * (NH * HD) + h * HD + lc * 2;
    float* d1 = g_opart[kv] + (size_t)row1 * (NH * HD) + h * HD + lc * 2;
    #pragma unroll
    for (int df = 0; df < 8; df++) {
        float2 u0 = { oacc[df][0] * inv0, oacc[df][1] * inv0 };
        float2 u1 = { oacc[df][2] * inv1, oacc[df][3] * inv1 };
        *(float2*)(d0 + df * 8) = u0;
        *(float2*)(d1 + df * 8) = u1;
    }
}

// ---------------------------------------------------------------------------
extern "C" void kernel_launch(void* const* d_in, const int* in_sizes, int n_in,
                              void* d_out, int out_size)
{
    const float* x  = (const float*)d_in[0];
    const float* Wq = (const float*)d_in[1];
    const float* Wk = (const float*)d_in[2];
    const float* Wv = (const float*)d_in[3];
    const float* Wo = (const float*)d_in[4];
    float* out = (float*)d_out;

    f2h_all_kernel<<<2304, 256>>>(x, Wq, Wk, Wv, Wo);
    qkv_kernel<<<dim3(32, 24), 128>>>();
    attn_kernel<<<dim3(32, 16, 4), 128>>>();
    reduce_o_kernel<<<1024, 256>>>();
    out_gemm_kernel<<<dim3(32, 16), 128>>>(out);
}

// round 10
// speedup vs baseline: 6.7611x; 1.0416x over previous
#include <cuda_runtime.h>
#include <cuda_fp16.h>
#include <cstdint>

#define S_LEN   2048
#define IN_DIM  512
#define OUT_DIM 512
#define NH      16
#define NKV     4
#define HD      64

// Q pre-scale: 1/sqrt(64) * log2(e)  (softmax done with ex2); folded into Wq.
#define SCALE_Q 0.18033688011112042f

// ---------------- scratch (__device__ globals; no cudaMalloc allowed) -------
__device__ __half g_xh[S_LEN * IN_DIM];            // x in fp16
__device__ __half g_wh[(NH * HD + 2 * NKV * HD) * IN_DIM];  // [Wq*s | Wk | Wv] fp16
__device__ __half g_woh[OUT_DIM * NH * HD];        // Wo fp16
__device__ __half g_qh[S_LEN * NH * HD];           // q fp16 (pre-scaled)
__device__ __half g_kh[S_LEN * NKV * HD];          // k fp16
__device__ __half g_vh[S_LEN * NKV * HD];          // v fp16
__device__ float g_opart[NKV][S_LEN * NH * HD];    // per-kv attention partials
__device__ __half g_oh[S_LEN * NH * HD];           // reduced attention output fp16

__device__ __forceinline__ float ex2f(float x) {
    float y; asm("ex2.approx.ftz.f32 %0, %1;" : "=f"(y) : "f"(x)); return y;
}
__device__ __forceinline__ uint32_t smem_u32(const void* p) {
    uint32_t a;
    asm("{ .reg .u64 t; cvta.to.shared.u64 t, %1; cvt.u32.u64 %0, t; }"
        : "=r"(a) : "l"(p));
    return a;
}
__device__ __forceinline__ uint64_t gmem_u64(const void* p) {
    uint64_t a;
    asm("cvta.to.global.u64 %0, %1;" : "=l"(a) : "l"(p));
    return a;
}

// m16n8k16 fp16 MMA, fp32 accumulate: C += A x B
__device__ __forceinline__ void mma16816(float* c, const uint32_t* a,
                                         uint32_t b0, uint32_t b1) {
    asm volatile(
        "mma.sync.aligned.m16n8k16.row.col.f32.f16.f16.f32 "
        "{%0,%1,%2,%3}, {%4,%5,%6,%7}, {%8,%9}, {%0,%1,%2,%3};"
        : "+f"(c[0]), "+f"(c[1]), "+f"(c[2]), "+f"(c[3])
        : "r"(a[0]), "r"(a[1]), "r"(a[2]), "r"(a[3]), "r"(b0), "r"(b1));
}
__device__ __forceinline__ void ldsm_x4(uint32_t& a, uint32_t& b, uint32_t& c,
                                        uint32_t& d, uint32_t addr) {
    asm volatile("ldmatrix.sync.aligned.m8n8.x4.shared.b16 {%0,%1,%2,%3}, [%4];"
                 : "=r"(a), "=r"(b), "=r"(c), "=r"(d) : "r"(addr));
}
__device__ __forceinline__ void ldsm_x4_t(uint32_t& a, uint32_t& b, uint32_t& c,
                                          uint32_t& d, uint32_t addr) {
    asm volatile("ldmatrix.sync.aligned.m8n8.x4.trans.shared.b16 {%0,%1,%2,%3}, [%4];"
                 : "=r"(a), "=r"(b), "=r"(c), "=r"(d) : "r"(addr));
}
__device__ __forceinline__ uint32_t packh2(float a, float b) {
    __half2 h = __floats2half2_rn(a, b);
    return *(uint32_t*)&h;
}

#define CP_ASYNC16(sm, gm) \
    asm volatile("cp.async.cg.shared.global [%0], [%1], 16;" :: "r"(sm), "l"(gm))
#define CP_COMMIT() asm volatile("cp.async.commit_group;" ::: "memory")
#define CP_WAIT0()  asm volatile("cp.async.wait_group 0;" ::: "memory")

// ---------------------------------------------------------------------------
// Fused fp32 -> fp16 convert for all 5 tensors. One float4 per thread.
// ---------------------------------------------------------------------------
__global__ __launch_bounds__(256)
void f2h_all_kernel(const float* __restrict__ x,  const float* __restrict__ wq,
                    const float* __restrict__ wk, const float* __restrict__ wv,
                    const float* __restrict__ wo)
{
    const int b = blockIdx.x;
    const float* src; __half* dst; int i; float scale = 1.0f;
    if (b < 1024)      { src = x;  dst = g_xh;  i = b * 256; }
    else if (b < 1536) { src = wq; dst = g_wh;  i = (b - 1024) * 256; scale = SCALE_Q; }
    else if (b < 1664) { src = wk; dst = g_wh + (NH * HD) * IN_DIM;            i = (b - 1536) * 256; }
    else if (b < 1792) { src = wv; dst = g_wh + (NH * HD + NKV * HD) * IN_DIM; i = (b - 1664) * 256; }
    else               { src = wo; dst = g_woh; i = (b - 1792) * 256; }
    i += threadIdx.x;
    float4 v = ((const float4*)src)[i];
    uint2 u = { packh2(v.x * scale, v.y * scale),
                packh2(v.z * scale, v.w * scale) };
    ((uint2*)dst)[i] = u;
}

// ---------------------------------------------------------------------------
// fp16 tensor-core GEMM body (unchanged from R8/R9).
// ---------------------------------------------------------------------------
struct HEpiQkv {
    __half* C; int ldc;
    template <int NF>
    __device__ __forceinline__ void operator()(float (&acc)[NF][4], int row0, int lc) const {
        #pragma unroll
        for (int nf = 0; nf < NF; nf++) {
            int col = nf * 8 + lc * 2;
            *(uint32_t*)&C[(size_t)row0 * ldc + col]       = packh2(acc[nf][0], acc[nf][1]);
            *(uint32_t*)&C[(size_t)(row0 + 8) * ldc + col] = packh2(acc[nf][2], acc[nf][3]);
        }
    }
};
struct HEpiOut {
    float* C;
    template <int NF>
    __device__ __forceinline__ void operator()(float (&acc)[NF][4], int row0, int lc) const {
        #pragma unroll
        for (int nf = 0; nf < NF; nf++) {
            int col = nf * 8 + lc * 2;
            float2 u0 = { acc[nf][0], acc[nf][1] };
            float2 u1 = { acc[nf][2], acc[nf][3] };
            *(float2*)&C[(size_t)row0 * OUT_DIM + col]       = u0;
            *(float2*)&C[(size_t)(row0 + 8) * OUT_DIM + col] = u1;
        }
    }
};

template <int NF, class EPI>
__device__ __forceinline__ void hgemm_body(
    const __half* __restrict__ A, const __half* __restrict__ Bn,
    int K, int m0, EPI epi)
{
    __shared__ __align__(16) __half sA[64 * 72];
    __shared__ __align__(16) __half sB[NF * 8 * 72];
    const int tid = threadIdx.x;
    const int w = tid >> 5, l = tid & 31;
    const int g8 = l >> 3, r8 = l & 7;
    const int lr = l >> 2, lc = l & 3;

    const uint32_t aA = smem_u32(sA) +
        ((w * 16 + (g8 & 1) * 8 + r8) * 72 + (g8 >> 1) * 8) * 2;
    const uint32_t aB = smem_u32(sB) +
        (((g8 >> 1) * 8 + r8) * 72 + (g8 & 1) * 8) * 2;

    float acc[NF][4] = {};

    const int nch = K >> 6;
    for (int kc = 0; kc < nch; kc++) {
        if (kc) __syncthreads();
        #pragma unroll
        for (int j = 0; j < 4; j++) {
            int u = tid * 4 + j;
            int row = u >> 3, c8 = u & 7;
            *(uint4*)(sA + row * 72 + c8 * 8) =
                *(const uint4*)(A + (size_t)(m0 + row) * K + kc * 64 + c8 * 8);
        }
        constexpr int PB = NF * 64 / 128;
        #pragma unroll
        for (int j = 0; j < PB; j++) {
            int u = tid * PB + j;
            int row = u >> 3, c8 = u & 7;
            *(uint4*)(sB + row * 72 + c8 * 8) =
                *(const uint4*)(Bn + (size_t)row * K + kc * 64 + c8 * 8);
        }
        __syncthreads();

        #pragma unroll
        for (int ks = 0; ks < 4; ks++) {
            uint32_t af[4];
            ldsm_x4(af[0], af[1], af[2], af[3], aA + ks * 16 * 2);
            #pragma unroll
            for (int ng = 0; ng < NF / 2; ng++) {
                uint32_t b0, b1, b2, b3;
                ldsm_x4(b0, b1, b2, b3, aB + (ng * 16 * 72 + ks * 16) * 2);
                mma16816(acc[2 * ng],     af, b0, b1);
                mma16816(acc[2 * ng + 1], af, b2, b3);
            }
        }
    }
    epi(acc, m0 + w * 16 + lr, lc);
}

// QKV projection (fp16 HMMA). grid (32, 24).
__global__ __launch_bounds__(128)
void qkv_kernel()
{
    const int by = blockIdx.y;
    const __half* Bn; __half* C; int ldc;
    if (by < 16) {
        Bn = g_wh + (size_t)(by * 64) * IN_DIM;
        C = g_qh + by * 64; ldc = NH * HD;
    } else if (by < 20) {
        Bn = g_wh + (size_t)(NH * HD + (by - 16) * 64) * IN_DIM;
        C = g_kh + (by - 16) * 64; ldc = NKV * HD;
    } else {
        Bn = g_wh + (size_t)(NH * HD + NKV * HD + (by - 20) * 64) * IN_DIM;
        C = g_vh + (by - 20) * 64; ldc = NKV * HD;
    }
    HEpiQkv epi = { C, ldc };
    hgemm_body<8>(g_xh, Bn, IN_DIM, blockIdx.x * 64, epi);
}

// Output projection (fp16 HMMA). grid (32, 16).
__global__ __launch_bounds__(128)
void out_gemm_kernel(float* __restrict__ out)
{
    const int n0 = blockIdx.y * 32;
    HEpiOut epi = { out + n0 };
    hgemm_body<4>(g_oh, g_woh + (size_t)n0 * (NH * HD), NH * HD, blockIdx.x * 64, epi);
}

// Sum kv partials -> fp16 g_oh. 8 floats / thread. grid 1024 x 256.
__global__ __launch_bounds__(256)
void reduce_o_kernel()
{
    int i = blockIdx.x * 256 + threadIdx.x;
    const float4* p0 = (const float4*)g_opart[0];
    const float4* p1 = (const float4*)g_opart[1];
    const float4* p2 = (const float4*)g_opart[2];
    const float4* p3 = (const float4*)g_opart[3];
    float4 a, b, r[2];
    #pragma unroll
    for (int j = 0; j < 2; j++) {
        int k = 2 * i + j;
        a = p0[k]; b = p1[k];
        r[j].x = a.x + b.x; r[j].y = a.y + b.y; r[j].z = a.z + b.z; r[j].w = a.w + b.w;
        a = p2[k]; b = p3[k];
        r[j].x += a.x + b.x; r[j].y += a.y + b.y; r[j].z += a.z + b.z; r[j].w += a.w + b.w;
    }
    uint4 u = { packh2(r[0].x, r[0].y), packh2(r[0].z, r[0].w),
                packh2(r[1].x, r[1].y), packh2(r[1].z, r[1].w) };
    ((uint4*)g_oh)[i] = u;
}

// ---------------------------------------------------------------------------
// mma.sync flash attention: cp.async double-buffered K/V, one sync per tile,
// row-sums via ones-column MMA, mask only on the diagonal tile.
// grid (32 s-blocks heavy-first, 16 h, 4 kv), 128 threads.
// ---------------------------------------------------------------------------
#define KP 72
#define BUFB (64 * KP * 2)       // bytes per K (or V) buffer
#define ONESF16 0x3C003C00u      // half2(1.0, 1.0)

__global__ __launch_bounds__(128)
void attn_kernel()
{
    __shared__ __align__(16) __half sK[2][64 * KP];
    __shared__ __align__(16) __half sV[2][64 * KP];

    const int tid = threadIdx.x;
    const int w   = tid >> 5;
    const int l   = tid & 31;
    const int lr  = l >> 2;
    const int lc  = l & 3;
    const int bs  = 31 - (int)blockIdx.x;   // heavy blocks first
    const int h   = blockIdx.y;
    const int kv  = blockIdx.z;
    const int s0  = bs * 64;
    const int T   = bs + 1;

    // ---- Q A-fragments, loaded once ---------------------------------------
    uint32_t qf[4][4];
    {
        const __half* qb = g_qh + (size_t)(s0 + w * 16) * (NH * HD) + h * HD;
        #pragma unroll
        for (int ks = 0; ks < 4; ks++) {
            int k0 = ks * 16 + lc * 2;
            qf[ks][0] = *(const uint32_t*)(qb + (size_t)lr * (NH * HD) + k0);
            qf[ks][1] = *(const uint32_t*)(qb + (size_t)(lr + 8) * (NH * HD) + k0);
            qf[ks][2] = *(const uint32_t*)(qb + (size_t)lr * (NH * HD) + k0 + 8);
            qf[ks][3] = *(const uint32_t*)(qb + (size_t)(lr + 8) * (NH * HD) + k0 + 8);
        }
    }

    const int g8 = l >> 3, r8 = l & 7;
    const uint32_t aK = smem_u32(sK) +
        (((g8 >> 1) * 8 + r8) * KP + (g8 & 1) * 8) * 2;
    const uint32_t aV = smem_u32(sV) +
        (((g8 & 1) * 8 + r8) * KP + (g8 >> 1) * 8) * 2;

    float oacc[8][4] = {};
    float lacc[4] = {};                     // ones-MMA row sums
    const int row0 = s0 + w * 16 + lr;
    const int row1 = row0 + 8;

    // K/V stager: thread covers half a row (64 B) of each tile. cp.async x8.
    const int key = tid >> 1, hf = tid & 1;
    const uint64_t kg0 = gmem_u64(g_kh + (size_t)key * (NKV * HD) + kv * HD + hf * 32);
    const uint64_t vg0 = gmem_u64(g_vh + (size_t)key * (NKV * HD) + kv * HD + hf * 32);
    const uint32_t sk0 = smem_u32(sK) + (key * KP + hf * 32) * 2;
    const uint32_t sv0 = smem_u32(sV) + (key * KP + hf * 32) * 2;

    // prologue: stage tile 0 into buffer 0
    #pragma unroll
    for (int j = 0; j < 4; j++) {
        CP_ASYNC16(sk0 + j * 16, kg0 + j * 16);
        CP_ASYNC16(sv0 + j * 16, vg0 + j * 16);
    }
    CP_COMMIT();

    for (int t = 0; t < T; t++) {
        const int buf = t & 1;
        CP_WAIT0();            // tile t landed (only outstanding group)
        __syncthreads();       // visible to all; all reads of buf^1 done

        // stage tile t+1 into the other buffer (race-free: after barrier)
        if (t + 1 < T) {
            const uint64_t kg = kg0 + (size_t)(t + 1) * 64 * (NKV * HD) * 2;
            const uint64_t vg = vg0 + (size_t)(t + 1) * 64 * (NKV * HD) * 2;
            const uint32_t sk = sk0 + (buf ^ 1) * BUFB;
            const uint32_t sv = sv0 + (buf ^ 1) * BUFB;
            #pragma unroll
            for (int j = 0; j < 4; j++) {
                CP_ASYNC16(sk + j * 16, kg + j * 16);
                CP_ASYNC16(sv + j * 16, vg + j * 16);
            }
            CP_COMMIT();
        }

        const uint32_t bK = aK + buf * BUFB;
        const uint32_t bV = aV + buf * BUFB;

        // ---- S = Q K^T ----------------------------------------------------
        float sc[8][4] = {};
        #pragma unroll
        for (int ks = 0; ks < 4; ks++) {
            #pragma unroll
            for (int kg = 0; kg < 4; kg++) {
                uint32_t b0, b1, b2, b3;
                ldsm_x4(b0, b1, b2, b3, bK + (kg * 16 * KP + ks * 16) * 2);
                mma16816(sc[2 * kg],     qf[ks], b0, b1);
                mma16816(sc[2 * kg + 1], qf[ks], b2, b3);
            }
        }

        // ---- exp (un-normalized); mask only on diagonal tile --------------
        uint32_t pf[4][4];
        if (t < T - 1) {
            #pragma unroll
            for (int nf = 0; nf < 8; nf++) {
                float p00 = ex2f(sc[nf][0]);
                float p01 = ex2f(sc[nf][1]);
                float p10 = ex2f(sc[nf][2]);
                float p11 = ex2f(sc[nf][3]);
                pf[nf >> 1][(nf & 1) * 2 + 0] = packh2(p00, p01);
                pf[nf >> 1][(nf & 1) * 2 + 1] = packh2(p10, p11);
            }
        } else {
            const int jb = t * 64;
            #pragma unroll
            for (int nf = 0; nf < 8; nf++) {
                int j0 = jb + nf * 8 + lc * 2;
                float p00 = (j0     <= row0) ? ex2f(sc[nf][0]) : 0.f;
                float p01 = (j0 + 1 <= row0) ? ex2f(sc[nf][1]) : 0.f;
                float p10 = (j0     <= row1) ? ex2f(sc[nf][2]) : 0.f;
                float p11 = (j0 + 1 <= row1) ? ex2f(sc[nf][3]) : 0.f;
                pf[nf >> 1][(nf & 1) * 2 + 0] = packh2(p00, p01);
                pf[nf >> 1][(nf & 1) * 2 + 1] = packh2(p10, p11);
            }
        }

        // ---- O += P V, lsum += P @ ones -----------------------------------
        #pragma unroll
        for (int ksg = 0; ksg < 4; ksg++) {
            mma16816(lacc, pf[ksg], ONESF16, ONESF16);
            #pragma unroll
            for (int nfp = 0; nfp < 4; nfp++) {
                uint32_t b0, b1, b2, b3;
                ldsm_x4_t(b0, b1, b2, b3, bV + (ksg * 16 * KP + nfp * 16) * 2);
                mma16816(oacc[2 * nfp],     pf[ksg], b0, b1);
                mma16816(oacc[2 * nfp + 1], pf[ksg], b2, b3);
            }
        }
    }

    // lacc already holds full cross-lane row sums (MMA reduces over k)
    const float inv0 = 0.25f / lacc[0];
    const float inv1 = 0.25f / lacc[2];

    float* d0 = g_opart[kv] + (size_t)row0 * (NH * HD) + h * HD + lc * 2;
    float* d1 = g_opart[kv] + (size_t)row1 * (NH * HD) + h * HD + lc * 2;
    #pragma unroll
    for (int df = 0; df < 8; df++) {
        float2 u0 = { oacc[df][0] * inv0, oacc[df][1] * inv0 };
        float2 u1 = { oacc[df][2] * inv1, oacc[df][3] * inv1 };
        *(float2*)(d0 + df * 8) = u0;
        *(float2*)(d1 + df * 8) = u1;
    }
}

// ---------------------------------------------------------------------------
extern "C" void kernel_launch(void* const* d_in, const int* in_sizes, int n_in,
                              void* d_out, int out_size)
{
    const float* x  = (const float*)d_in[0];
    const float* Wq = (const float*)d_in[1];
    const float* Wk = (const float*)d_in[2];
    const float* Wv = (const float*)d_in[3];
    const float* Wo = (const float*)d_in[4];
    float* out = (float*)d_out;

    f2h_all_kernel<<<2304, 256>>>(x, Wq, Wk, Wv, Wo);
    qkv_kernel<<<dim3(32, 24), 128>>>();
    attn_kernel<<<dim3(32, 16, 4), 128>>>();
    reduce_o_kernel<<<1024, 256>>>();
    out_gemm_kernel<<<dim3(32, 16), 128>>>(out);
}